// round 2
// baseline (speedup 1.0000x reference)
#include <cuda_runtime.h>
#include <cuda_bf16.h>

// Problem constants (fixed shapes)
#define BDIM 8
#define NDIM 256
#define HDIM 128
#define INDIM 259
#define NODES (BDIM * NDIM)  // 2048

// ---------------- device scratch (no allocations allowed) ----------------
__device__ float g_P[NODES * HDIM];       // W1[:, 0:128]   @ x_emb  (per node)
__device__ float g_Q[NODES * HDIM];       // W1[:, 128:256] @ x_emb  (per node)
__device__ float g_b1eff[HDIM];           // b1 + W1c @ bd
__device__ __nv_bfloat16 g_Wfuse[HDIM * HDIM];  // W1c @ Wd  [h][k]
__device__ __nv_bfloat16 g_W2bf[HDIM * HDIM];   // W2 bf16   [g][h]

// ---------------- helpers ----------------
__device__ __forceinline__ unsigned pack_bf2(float a, float b) {
    unsigned short lo = __bfloat16_as_ushort(__float2bfloat16_rn(a));
    unsigned short hi = __bfloat16_as_ushort(__float2bfloat16_rn(b));
    return (unsigned)lo | ((unsigned)hi << 16);
}

__device__ __forceinline__ float silu_f(float x) {
    return __fdividef(x, 1.0f + __expf(-x));
}

// ---------------- prep kernel 1: fused weights ----------------
__global__ void prep_weights(const float* __restrict__ Wd,
                             const float* __restrict__ bd,
                             const float* __restrict__ W1,
                             const float* __restrict__ b1,
                             const float* __restrict__ W2) {
    int h = threadIdx.x;  // 0..127
    float w1c0 = W1[h * INDIM + 2 * HDIM + 0];
    float w1c1 = W1[h * INDIM + 2 * HDIM + 1];
    float w1c2 = W1[h * INDIM + 2 * HDIM + 2];
    g_b1eff[h] = b1[h] + w1c0 * bd[0] + w1c1 * bd[1] + w1c2 * bd[2];
#pragma unroll 4
    for (int k = 0; k < HDIM; k++) {
        float v = w1c0 * Wd[0 * HDIM + k] + w1c1 * Wd[1 * HDIM + k] + w1c2 * Wd[2 * HDIM + k];
        g_Wfuse[h * HDIM + k] = __float2bfloat16_rn(v);
    }
#pragma unroll 4
    for (int k = 0; k < HDIM; k++)
        g_W2bf[h * HDIM + k] = __float2bfloat16_rn(W2[h * HDIM + k]);
}

// ---------------- prep kernel 2: per-node P/Q ----------------
// grid = 128 blocks, 128 threads; each block handles 16 nodes.
__global__ void prep_pq(const float* __restrict__ x_emb,
                        const float* __restrict__ W1) {
    __shared__ float xs[16][HDIM];
    int t = threadIdx.x;
    int r0 = blockIdx.x * 16;
    for (int idx = t; idx < 16 * HDIM; idx += 128)
        xs[idx >> 7][idx & 127] = x_emb[r0 * HDIM + idx];
    __syncthreads();

    float p[16], q[16];
#pragma unroll
    for (int ii = 0; ii < 16; ii++) { p[ii] = 0.f; q[ii] = 0.f; }
    const float* w1r = W1 + t * INDIM;
#pragma unroll 4
    for (int k = 0; k < HDIM; k++) {
        float wa = __ldg(&w1r[k]);
        float wb = __ldg(&w1r[HDIM + k]);
#pragma unroll
        for (int ii = 0; ii < 16; ii++) {
            float xv = xs[ii][k];
            p[ii] = fmaf(wa, xv, p[ii]);
            q[ii] = fmaf(wb, xv, q[ii]);
        }
    }
#pragma unroll
    for (int ii = 0; ii < 16; ii++) {
        g_P[(r0 + ii) * HDIM + t] = p[ii];
        g_Q[(r0 + ii) * HDIM + t] = q[ii];
    }
}

// ---------------- main fused kernel ----------------
// One CTA per (b, i). 512 threads = 16 warps in a 4(M) x 4(N) grid.
// GEMM1: H1[256x128] = silu( pair[256x128] @ Wfuse^T + P[i] + Q[j] + b1eff )
// GEMM2: H2[256x128] = silu( H1 @ W2^T + b2 );  s[j] = H2 @ W3
// out[b,i,:] = pos[b,i,:] + sum_j coord_diff * s[j] * pair_mask

#define PA 136  // smem pitch in bf16 elements (128 + 8 pad -> conflict-free)

// smem byte offsets
#define OFF_AS   0            // 256*136*2 = 69632   (A tile, reused for H1)
#define OFF_QS   69632        // 256*136*2 = 69632   (Q rows, bf16)
#define OFF_B1   139264       // 128*136*2 = 34816   (Wfuse [h][k])
#define OFF_B2   174080       // 128*136*2 = 34816   (W2    [g][h])
#define OFF_BIAS 208896       // float[128]  P[i]+b1eff
#define OFF_W3   209408       // float[128]
#define OFF_B2V  209920       // float[128]
#define OFF_SRED 210432       // float[256]
#define OFF_RED3 211456       // float[16*3]
#define SMEM_TOTAL 211648

__device__ __forceinline__ void do_gemm(const __nv_bfloat16* __restrict__ Abase,
                                        const __nv_bfloat16* __restrict__ Bbase,
                                        float acc[4][4][4]) {
#pragma unroll
    for (int ks = 0; ks < 8; ks++) {
        const int k0 = ks * 16;
        unsigned a[4][4], bf[4][2];
#pragma unroll
        for (int mt = 0; mt < 4; mt++) {
            const __nv_bfloat16* p = Abase + mt * (16 * PA) + k0;
            a[mt][0] = *reinterpret_cast<const unsigned*>(p);
            a[mt][1] = *reinterpret_cast<const unsigned*>(p + 8 * PA);
            a[mt][2] = *reinterpret_cast<const unsigned*>(p + 8);
            a[mt][3] = *reinterpret_cast<const unsigned*>(p + 8 * PA + 8);
        }
#pragma unroll
        for (int nt = 0; nt < 4; nt++) {
            const __nv_bfloat16* p = Bbase + nt * (8 * PA) + k0;
            bf[nt][0] = *reinterpret_cast<const unsigned*>(p);
            bf[nt][1] = *reinterpret_cast<const unsigned*>(p + 8);
        }
#pragma unroll
        for (int mt = 0; mt < 4; mt++)
#pragma unroll
            for (int nt = 0; nt < 4; nt++)
                asm volatile(
                    "mma.sync.aligned.m16n8k16.row.col.f32.bf16.bf16.f32 "
                    "{%0,%1,%2,%3}, {%4,%5,%6,%7}, {%8,%9}, {%0,%1,%2,%3};\n"
                    : "+f"(acc[mt][nt][0]), "+f"(acc[mt][nt][1]),
                      "+f"(acc[mt][nt][2]), "+f"(acc[mt][nt][3])
                    : "r"(a[mt][0]), "r"(a[mt][1]), "r"(a[mt][2]), "r"(a[mt][3]),
                      "r"(bf[nt][0]), "r"(bf[nt][1]));
    }
}

__global__ __launch_bounds__(512, 1)
void pos_update_main(const float* __restrict__ pair_emb,
                     const float* __restrict__ pos,
                     const float* __restrict__ coord_diff,
                     const float* __restrict__ pair_mask,
                     const float* __restrict__ b2,
                     const float* __restrict__ W3,
                     float* __restrict__ out) {
    extern __shared__ char smem[];
    __nv_bfloat16* As  = reinterpret_cast<__nv_bfloat16*>(smem + OFF_AS);
    __nv_bfloat16* Qs  = reinterpret_cast<__nv_bfloat16*>(smem + OFF_QS);
    __nv_bfloat16* Bs1 = reinterpret_cast<__nv_bfloat16*>(smem + OFF_B1);
    __nv_bfloat16* Bs2 = reinterpret_cast<__nv_bfloat16*>(smem + OFF_B2);
    float* biasI = reinterpret_cast<float*>(smem + OFF_BIAS);
    float* w3s   = reinterpret_cast<float*>(smem + OFF_W3);
    float* b2s   = reinterpret_cast<float*>(smem + OFF_B2V);
    float* sRed  = reinterpret_cast<float*>(smem + OFF_SRED);
    float* red3  = reinterpret_cast<float*>(smem + OFF_RED3);

    const int tid  = threadIdx.x;
    const int lane = tid & 31;
    const int warp = tid >> 5;
    const int wm = warp >> 2, wn = warp & 3;
    const int g = lane >> 2, l4 = lane & 3;
    const int blk = blockIdx.x;               // b*256 + i
    const int bbase = blk & ~255;             // b*256

    // ---- load A tile (pair_emb row-block, fp32 -> bf16, swizzle-free padded) ----
    {
        const float4* src = reinterpret_cast<const float4*>(pair_emb + (size_t)blk * (NDIM * HDIM));
#pragma unroll
        for (int it = 0; it < 16; it++) {
            int idx = tid + it * 512;         // 0..8191
            float4 f = src[idx];
            int r = idx >> 5;                 // 32 float4 per row
            int c = (idx & 31) << 2;
            uint2 v;
            v.x = pack_bf2(f.x, f.y);
            v.y = pack_bf2(f.z, f.w);
            *reinterpret_cast<uint2*>(As + r * PA + c) = v;
        }
        // Q rows for this batch (g_Q is fp32; L2-resident across the 256 CTAs of a batch)
        const float4* qsrc = reinterpret_cast<const float4*>(g_Q + (size_t)bbase * HDIM);
#pragma unroll
        for (int it = 0; it < 16; it++) {
            int idx = tid + it * 512;
            float4 f = qsrc[idx];
            int r = idx >> 5;
            int c = (idx & 31) << 2;
            uint2 v;
            v.x = pack_bf2(f.x, f.y);
            v.y = pack_bf2(f.z, f.w);
            *reinterpret_cast<uint2*>(Qs + r * PA + c) = v;
        }
        // weight tiles (bf16, contiguous -> padded pitch)
        const uint4* w1src = reinterpret_cast<const uint4*>(g_Wfuse);
        const uint4* w2src = reinterpret_cast<const uint4*>(g_W2bf);
#pragma unroll
        for (int it = 0; it < 4; it++) {
            int idx = tid + it * 512;         // 0..2047 (16 uint4 per 128-bf16 row)
            int r = idx >> 4;
            int c = (idx & 15) << 3;
            *reinterpret_cast<uint4*>(Bs1 + r * PA + c) = w1src[idx];
            *reinterpret_cast<uint4*>(Bs2 + r * PA + c) = w2src[idx];
        }
        if (tid < 128) {
            biasI[tid] = g_P[(size_t)blk * HDIM + tid] + g_b1eff[tid];
            w3s[tid] = W3[tid];
            b2s[tid] = b2[tid];
        }
        if (tid < 256) sRed[tid] = 0.f;
    }
    __syncthreads();

    float acc[4][4][4];

    // ---- GEMM1 ----
#pragma unroll
    for (int mt = 0; mt < 4; mt++)
#pragma unroll
        for (int nt = 0; nt < 4; nt++)
#pragma unroll
            for (int e = 0; e < 4; e++) acc[mt][nt][e] = 0.f;

    do_gemm(As + (wm * 64 + g) * PA + l4 * 2,
            Bs1 + (wn * 32 + g) * PA + l4 * 2, acc);

    __syncthreads();  // everyone done reading As before H1 overwrite

    // ---- epilogue 1: + bias + Q, silu, store H1 into As ----
#pragma unroll
    for (int mt = 0; mt < 4; mt++) {
        int r = wm * 64 + mt * 16 + g;
#pragma unroll
        for (int nt = 0; nt < 4; nt++) {
            int c = wn * 32 + nt * 8 + l4 * 2;
            unsigned qlo = *reinterpret_cast<const unsigned*>(Qs + r * PA + c);
            unsigned qhi = *reinterpret_cast<const unsigned*>(Qs + (r + 8) * PA + c);
            __nv_bfloat162 ql = *reinterpret_cast<__nv_bfloat162*>(&qlo);
            __nv_bfloat162 qh = *reinterpret_cast<__nv_bfloat162*>(&qhi);
            float bc0 = biasI[c], bc1 = biasI[c + 1];
            float x0 = acc[mt][nt][0] + bc0 + __bfloat162float(ql.x);
            float x1 = acc[mt][nt][1] + bc1 + __bfloat162float(ql.y);
            float x2 = acc[mt][nt][2] + bc0 + __bfloat162float(qh.x);
            float x3 = acc[mt][nt][3] + bc1 + __bfloat162float(qh.y);
            x0 = silu_f(x0); x1 = silu_f(x1); x2 = silu_f(x2); x3 = silu_f(x3);
            *reinterpret_cast<unsigned*>(As + r * PA + c)       = pack_bf2(x0, x1);
            *reinterpret_cast<unsigned*>(As + (r + 8) * PA + c) = pack_bf2(x2, x3);
        }
    }
    __syncthreads();

    // ---- GEMM2 ----
#pragma unroll
    for (int mt = 0; mt < 4; mt++)
#pragma unroll
        for (int nt = 0; nt < 4; nt++)
#pragma unroll
            for (int e = 0; e < 4; e++) acc[mt][nt][e] = 0.f;

    do_gemm(As + (wm * 64 + g) * PA + l4 * 2,
            Bs2 + (wn * 32 + g) * PA + l4 * 2, acc);

    // ---- epilogue 2: silu, dot with W3, reduce over columns ----
    float sAcc[4][2];
#pragma unroll
    for (int mt = 0; mt < 4; mt++) { sAcc[mt][0] = 0.f; sAcc[mt][1] = 0.f; }
#pragma unroll
    for (int mt = 0; mt < 4; mt++) {
#pragma unroll
        for (int nt = 0; nt < 4; nt++) {
            int c = wn * 32 + nt * 8 + l4 * 2;
            float bb0 = b2s[c], bb1 = b2s[c + 1];
            float w30 = w3s[c], w31 = w3s[c + 1];
            float y0 = silu_f(acc[mt][nt][0] + bb0);
            float y1 = silu_f(acc[mt][nt][1] + bb1);
            float y2 = silu_f(acc[mt][nt][2] + bb0);
            float y3 = silu_f(acc[mt][nt][3] + bb1);
            sAcc[mt][0] += y0 * w30 + y1 * w31;
            sAcc[mt][1] += y2 * w30 + y3 * w31;
        }
    }
    // quad reduce (over l4) -> per-row partial over this warp's 32 columns
#pragma unroll
    for (int mt = 0; mt < 4; mt++) {
#pragma unroll
        for (int hh = 0; hh < 2; hh++) {
            sAcc[mt][hh] += __shfl_xor_sync(0xffffffffu, sAcc[mt][hh], 1);
            sAcc[mt][hh] += __shfl_xor_sync(0xffffffffu, sAcc[mt][hh], 2);
        }
    }
    if (l4 == 0) {
#pragma unroll
        for (int mt = 0; mt < 4; mt++) {
            atomicAdd(&sRed[wm * 64 + mt * 16 + g],     sAcc[mt][0]);
            atomicAdd(&sRed[wm * 64 + mt * 16 + 8 + g], sAcc[mt][1]);
        }
    }
    __syncthreads();

    // ---- final: trans = coord_diff * s * mask, sum over j, add pos ----
    float t0 = 0.f, t1 = 0.f, t2 = 0.f;
    if (tid < 256) {
        int j = tid;
        float sj = sRed[j] * pair_mask[(size_t)blk * NDIM + j];
        const float* cd = coord_diff + ((size_t)blk * NDIM + j) * 3;
        t0 = cd[0] * sj; t1 = cd[1] * sj; t2 = cd[2] * sj;
    }
#pragma unroll
    for (int off = 16; off > 0; off >>= 1) {
        t0 += __shfl_down_sync(0xffffffffu, t0, off);
        t1 += __shfl_down_sync(0xffffffffu, t1, off);
        t2 += __shfl_down_sync(0xffffffffu, t2, off);
    }
    if (lane == 0) {
        red3[warp * 3 + 0] = t0;
        red3[warp * 3 + 1] = t1;
        red3[warp * 3 + 2] = t2;
    }
    __syncthreads();
    if (tid < 3) {
        float s = 0.f;
#pragma unroll
        for (int w = 0; w < 16; w++) s += red3[w * 3 + tid];
        out[blk * 3 + tid] = pos[blk * 3 + tid] + s;
    }
}

// ---------------- launcher ----------------
extern "C" void kernel_launch(void* const* d_in, const int* in_sizes, int n_in,
                              void* d_out, int out_size) {
    const float* x_emb      = (const float*)d_in[0];
    const float* pair_emb   = (const float*)d_in[1];
    const float* pos        = (const float*)d_in[2];
    const float* coord_diff = (const float*)d_in[3];
    // d_in[4] = node_mask (unused by the reference output)
    const float* pair_mask  = (const float*)d_in[5];
    const float* Wd         = (const float*)d_in[6];
    const float* bd         = (const float*)d_in[7];
    const float* W1         = (const float*)d_in[8];
    const float* b1         = (const float*)d_in[9];
    const float* W2         = (const float*)d_in[10];
    const float* b2         = (const float*)d_in[11];
    const float* W3         = (const float*)d_in[12];
    float* out = (float*)d_out;

    cudaFuncSetAttribute(pos_update_main,
                         cudaFuncAttributeMaxDynamicSharedMemorySize, SMEM_TOTAL);

    prep_weights<<<1, 128>>>(Wd, bd, W1, b1, W2);
    prep_pq<<<NODES / 16, 128>>>(x_emb, W1);
    pos_update_main<<<NODES, 512, SMEM_TOTAL>>>(pair_emb, pos, coord_diff,
                                                pair_mask, b2, W3, out);
    (void)in_sizes; (void)n_in; (void)out_size;
}

// round 4
// speedup vs baseline: 1.2418x; 1.2418x over previous
#include <cuda_runtime.h>
#include <cuda_bf16.h>
#include <cstdint>

#define BDIM 8
#define NDIM 256
#define HDIM 128
#define INDIM 259
#define NODES (BDIM * NDIM)  // 2048

// ---------------- device scratch ----------------
__device__ float g_P[NODES * HDIM];                 // W1a @ x (per node, fp32)
__device__ __nv_bfloat16 g_Qbf[NODES * HDIM];       // W1b @ x (per node, bf16)
__device__ float g_b1eff[HDIM];                     // b1 + W1c @ bd
__device__ __nv_bfloat16 g_Wfuse[HDIM * HDIM];      // W1c @ Wd  [h][k]
__device__ __nv_bfloat16 g_W2bf[HDIM * HDIM];       // W2        [g][h]

// ---------------- helpers ----------------
__device__ __forceinline__ unsigned pack_bf2(float a, float b) {
    unsigned short lo = __bfloat16_as_ushort(__float2bfloat16_rn(a));
    unsigned short hi = __bfloat16_as_ushort(__float2bfloat16_rn(b));
    return (unsigned)lo | ((unsigned)hi << 16);
}
__device__ __forceinline__ float tanh_approx(float x) {
    float y; asm("tanh.approx.f32 %0, %1;" : "=f"(y) : "f"(x)); return y;
}
__device__ __forceinline__ float silu_f(float x) {
    // silu(x) = 0.5x * (1 + tanh(x/2))
    float h = 0.5f * x;
    return fmaf(h, tanh_approx(h), h);
}
__device__ __forceinline__ uint32_t smem_u32(const void* p) {
    uint32_t a;
    asm("{ .reg .u64 t; cvta.to.shared.u64 t, %1; cvt.u32.u64 %0, t; }" : "=r"(a) : "l"(p));
    return a;
}

// ---------------- prep kernel (fused, 129 blocks) ----------------
__global__ void prep(const float* __restrict__ x_emb, const float* __restrict__ Wd,
                     const float* __restrict__ bd, const float* __restrict__ W1,
                     const float* __restrict__ b1, const float* __restrict__ W2) {
    int t = threadIdx.x;
    if (blockIdx.x == 128) {
        float w1c0 = W1[t * INDIM + 2 * HDIM + 0];
        float w1c1 = W1[t * INDIM + 2 * HDIM + 1];
        float w1c2 = W1[t * INDIM + 2 * HDIM + 2];
        g_b1eff[t] = b1[t] + w1c0 * bd[0] + w1c1 * bd[1] + w1c2 * bd[2];
#pragma unroll 4
        for (int k = 0; k < HDIM; k++) {
            float v = w1c0 * Wd[k] + w1c1 * Wd[HDIM + k] + w1c2 * Wd[2 * HDIM + k];
            g_Wfuse[t * HDIM + k] = __float2bfloat16_rn(v);
            g_W2bf[t * HDIM + k]  = __float2bfloat16_rn(W2[t * HDIM + k]);
        }
        return;
    }
    __shared__ float xs[16][HDIM];
    int r0 = blockIdx.x * 16;
    for (int idx = t; idx < 16 * HDIM; idx += 128)
        xs[idx >> 7][idx & 127] = x_emb[r0 * HDIM + idx];
    __syncthreads();

    float p[16], q[16];
#pragma unroll
    for (int ii = 0; ii < 16; ii++) { p[ii] = 0.f; q[ii] = 0.f; }
    const float* w1r = W1 + t * INDIM;
#pragma unroll 4
    for (int k = 0; k < HDIM; k++) {
        float wa = __ldg(&w1r[k]);
        float wb = __ldg(&w1r[HDIM + k]);
#pragma unroll
        for (int ii = 0; ii < 16; ii++) {
            float xv = xs[ii][k];
            p[ii] = fmaf(wa, xv, p[ii]);
            q[ii] = fmaf(wb, xv, q[ii]);
        }
    }
#pragma unroll
    for (int ii = 0; ii < 16; ii++) {
        g_P[(r0 + ii) * HDIM + t]   = p[ii];
        g_Qbf[(r0 + ii) * HDIM + t] = __float2bfloat16_rn(q[ii]);
    }
}

// ---------------- main fused kernel (mma.sync + ldmatrix) ----------------
// One CTA per (b, i). 512 threads = 16 warps in a 4(M) x 4(N) grid.
// GEMM1: H1[256x128] = silu( pair[256x128] @ Wfuse^T + P[i] + Q[j] + b1eff )
// GEMM2: H2[256x128] = silu( H1 @ W2^T + b2 );  s[j] = H2 @ W3
// out[b,i,:] = pos[b,i,:] + sum_j coord_diff * s[j] * pair_mask

#define PA 136                 // smem pitch in bf16 (128 + 8 pad)
#define ROWB (PA * 2)          // 272 bytes per row (16B aligned)

#define OFF_AS   0             // 256*272 = 69632   (A tile, reused for H1)
#define OFF_QS   69632         // 256*272 = 69632   (Q rows, bf16)
#define OFF_B1   139264        // 128*272 = 34816   (Wfuse [h][k])
#define OFF_B2   174080        // 128*272 = 34816   (W2    [g][h])
#define OFF_BIAS 208896        // float[128]  P[i] + b1eff
#define OFF_W3   209408        // float[128]
#define OFF_B2V  209920        // float[128]
#define OFF_SRED 210432        // float[256]
#define OFF_RED3 211456        // float[16*3]
#define SMEM_TOTAL 211648

#define LDSM_X4(r0, r1, r2, r3, addr) \
    asm volatile("ldmatrix.sync.aligned.m8n8.x4.shared.b16 {%0,%1,%2,%3}, [%4];" \
                 : "=r"(r0), "=r"(r1), "=r"(r2), "=r"(r3) : "r"(addr))
#define LDSM_X2(r0, r1, addr) \
    asm volatile("ldmatrix.sync.aligned.m8n8.x2.shared.b16 {%0,%1}, [%2];" \
                 : "=r"(r0), "=r"(r1) : "r"(addr))

__device__ __forceinline__ void do_gemm(uint32_t aLane, uint32_t bLane,
                                        float acc[4][4][4]) {
#pragma unroll
    for (int ks = 0; ks < 8; ks++) {
        uint32_t a[4][4], b[4][2];
#pragma unroll
        for (int mt = 0; mt < 4; mt++)
            LDSM_X4(a[mt][0], a[mt][1], a[mt][2], a[mt][3],
                    aLane + mt * (16 * ROWB) + ks * 32);
#pragma unroll
        for (int nt = 0; nt < 4; nt++)
            LDSM_X2(b[nt][0], b[nt][1],
                    bLane + nt * (8 * ROWB) + ks * 32);
#pragma unroll
        for (int mt = 0; mt < 4; mt++)
#pragma unroll
            for (int nt = 0; nt < 4; nt++)
                asm volatile(
                    "mma.sync.aligned.m16n8k16.row.col.f32.bf16.bf16.f32 "
                    "{%0,%1,%2,%3}, {%4,%5,%6,%7}, {%8,%9}, {%0,%1,%2,%3};\n"
                    : "+f"(acc[mt][nt][0]), "+f"(acc[mt][nt][1]),
                      "+f"(acc[mt][nt][2]), "+f"(acc[mt][nt][3])
                    : "r"(a[mt][0]), "r"(a[mt][1]), "r"(a[mt][2]), "r"(a[mt][3]),
                      "r"(b[nt][0]), "r"(b[nt][1]));
    }
}

__global__ __launch_bounds__(512, 1)
void pos_update_main(const float* __restrict__ pair_emb,
                     const float* __restrict__ pos,
                     const float* __restrict__ coord_diff,
                     const float* __restrict__ pair_mask,
                     const float* __restrict__ b2,
                     const float* __restrict__ W3,
                     float* __restrict__ out) {
    extern __shared__ char smem[];
    __nv_bfloat16* As = reinterpret_cast<__nv_bfloat16*>(smem + OFF_AS);
    __nv_bfloat16* Qs = reinterpret_cast<__nv_bfloat16*>(smem + OFF_QS);
    float* biasI = reinterpret_cast<float*>(smem + OFF_BIAS);
    float* w3s   = reinterpret_cast<float*>(smem + OFF_W3);
    float* b2s   = reinterpret_cast<float*>(smem + OFF_B2V);
    float* sRed  = reinterpret_cast<float*>(smem + OFF_SRED);
    float* red3  = reinterpret_cast<float*>(smem + OFF_RED3);

    const uint32_t sb = smem_u32(smem);
    const int tid  = threadIdx.x;
    const int lane = tid & 31;
    const int warp = tid >> 5;
    const int wm = warp >> 2, wn = warp & 3;
    const int g = lane >> 2, l4 = lane & 3;
    const int blk = blockIdx.x;               // b*256 + i
    const int bbase = blk & ~255;             // b*256

    // per-lane ldmatrix base addresses
    const uint32_t aLane = sb + OFF_AS + (uint32_t)(wm * 64 + (lane & 15)) * ROWB
                              + (uint32_t)(lane >> 4) * 16;
    const uint32_t bLane1 = sb + OFF_B1 + (uint32_t)(wn * 32 + (lane & 7)) * ROWB
                              + (uint32_t)((lane >> 3) & 1) * 16;
    const uint32_t bLane2 = bLane1 + (OFF_B2 - OFF_B1);

    // ---- load phase ----
    {
        const float4* src = reinterpret_cast<const float4*>(pair_emb + (size_t)blk * (NDIM * HDIM));
#pragma unroll
        for (int it = 0; it < 16; it++) {
            int idx = tid + it * 512;         // 8192 float4
            float4 f = src[idx];
            int r = idx >> 5;                 // 32 float4 per row
            int c = (idx & 31) << 2;
            uint2 v; v.x = pack_bf2(f.x, f.y); v.y = pack_bf2(f.z, f.w);
            *reinterpret_cast<uint2*>(As + r * PA + c) = v;
        }
        // Q rows (bf16, L2-resident across the 256 CTAs of a batch)
        const uint4* qsrc = reinterpret_cast<const uint4*>(g_Qbf + (size_t)bbase * HDIM);
#pragma unroll
        for (int it = 0; it < 8; it++) {
            int idx = tid + it * 512;         // 4096 uint4 (16 per 128-bf16 row)
            int r = idx >> 4;
            int c = (idx & 15) << 3;
            *reinterpret_cast<uint4*>(Qs + r * PA + c) = qsrc[idx];
        }
        // weight tiles
        const uint4* w1 = reinterpret_cast<const uint4*>(g_Wfuse);
        const uint4* w2 = reinterpret_cast<const uint4*>(g_W2bf);
        __nv_bfloat16* Bs1 = reinterpret_cast<__nv_bfloat16*>(smem + OFF_B1);
        __nv_bfloat16* Bs2 = reinterpret_cast<__nv_bfloat16*>(smem + OFF_B2);
#pragma unroll
        for (int it = 0; it < 4; it++) {
            int idx = tid + it * 512;         // 2048 uint4
            int r = idx >> 4;
            int c = (idx & 15) << 3;
            *reinterpret_cast<uint4*>(Bs1 + r * PA + c) = w1[idx];
            *reinterpret_cast<uint4*>(Bs2 + r * PA + c) = w2[idx];
        }
        if (tid < 128) {
            biasI[tid] = g_P[(size_t)blk * HDIM + tid] + g_b1eff[tid];
            w3s[tid] = W3[tid];
            b2s[tid] = b2[tid];
        }
        if (tid < 256) sRed[tid] = 0.f;
    }
    __syncthreads();

    float acc[4][4][4];

    // ---- GEMM1 ----
#pragma unroll
    for (int mt = 0; mt < 4; mt++)
#pragma unroll
        for (int nt = 0; nt < 4; nt++)
#pragma unroll
            for (int e = 0; e < 4; e++) acc[mt][nt][e] = 0.f;

    do_gemm(aLane, bLane1, acc);

    __syncthreads();  // all reads of As done before H1 overwrite

    // ---- epilogue 1: silu(acc + biasI + Q) -> H1 bf16 into As ----
#pragma unroll
    for (int mt = 0; mt < 4; mt++) {
        int r = wm * 64 + mt * 16 + g;
#pragma unroll
        for (int nt = 0; nt < 4; nt++) {
            int c = wn * 32 + nt * 8 + l4 * 2;
            unsigned qlo = *reinterpret_cast<const unsigned*>(Qs + r * PA + c);
            unsigned qhi = *reinterpret_cast<const unsigned*>(Qs + (r + 8) * PA + c);
            __nv_bfloat162 ql = *reinterpret_cast<__nv_bfloat162*>(&qlo);
            __nv_bfloat162 qh = *reinterpret_cast<__nv_bfloat162*>(&qhi);
            float bc0 = biasI[c], bc1 = biasI[c + 1];
            float x0 = acc[mt][nt][0] + bc0 + __bfloat162float(ql.x);
            float x1 = acc[mt][nt][1] + bc1 + __bfloat162float(ql.y);
            float x2 = acc[mt][nt][2] + bc0 + __bfloat162float(qh.x);
            float x3 = acc[mt][nt][3] + bc1 + __bfloat162float(qh.y);
            *reinterpret_cast<unsigned*>(As + r * PA + c)       = pack_bf2(silu_f(x0), silu_f(x1));
            *reinterpret_cast<unsigned*>(As + (r + 8) * PA + c) = pack_bf2(silu_f(x2), silu_f(x3));
        }
    }
    __syncthreads();

    // ---- GEMM2 ----
#pragma unroll
    for (int mt = 0; mt < 4; mt++)
#pragma unroll
        for (int nt = 0; nt < 4; nt++)
#pragma unroll
            for (int e = 0; e < 4; e++) acc[mt][nt][e] = 0.f;

    do_gemm(aLane, bLane2, acc);

    // ---- epilogue 2: silu, dot with W3, reduce over columns ----
    float sAcc[4][2];
#pragma unroll
    for (int mt = 0; mt < 4; mt++) { sAcc[mt][0] = 0.f; sAcc[mt][1] = 0.f; }
#pragma unroll
    for (int mt = 0; mt < 4; mt++) {
#pragma unroll
        for (int nt = 0; nt < 4; nt++) {
            int c = wn * 32 + nt * 8 + l4 * 2;
            float bb0 = b2s[c], bb1 = b2s[c + 1];
            float w30 = w3s[c], w31 = w3s[c + 1];
            float y0 = silu_f(acc[mt][nt][0] + bb0);
            float y1 = silu_f(acc[mt][nt][1] + bb1);
            float y2 = silu_f(acc[mt][nt][2] + bb0);
            float y3 = silu_f(acc[mt][nt][3] + bb1);
            sAcc[mt][0] += y0 * w30 + y1 * w31;
            sAcc[mt][1] += y2 * w30 + y3 * w31;
        }
    }
#pragma unroll
    for (int mt = 0; mt < 4; mt++) {
#pragma unroll
        for (int hh = 0; hh < 2; hh++) {
            sAcc[mt][hh] += __shfl_xor_sync(0xffffffffu, sAcc[mt][hh], 1);
            sAcc[mt][hh] += __shfl_xor_sync(0xffffffffu, sAcc[mt][hh], 2);
        }
    }
    if (l4 == 0) {
#pragma unroll
        for (int mt = 0; mt < 4; mt++) {
            atomicAdd(&sRed[wm * 64 + mt * 16 + g],     sAcc[mt][0]);
            atomicAdd(&sRed[wm * 64 + mt * 16 + 8 + g], sAcc[mt][1]);
        }
    }
    __syncthreads();

    // ---- final: trans = coord_diff * s * mask, sum over j, add pos ----
    float t0 = 0.f, t1 = 0.f, t2 = 0.f;
    if (tid < 256) {
        int j = tid;
        float sj = sRed[j] * pair_mask[(size_t)blk * NDIM + j];
        const float* cd = coord_diff + ((size_t)blk * NDIM + j) * 3;
        t0 = cd[0] * sj; t1 = cd[1] * sj; t2 = cd[2] * sj;
    }
#pragma unroll
    for (int off = 16; off > 0; off >>= 1) {
        t0 += __shfl_down_sync(0xffffffffu, t0, off);
        t1 += __shfl_down_sync(0xffffffffu, t1, off);
        t2 += __shfl_down_sync(0xffffffffu, t2, off);
    }
    if (lane == 0) {
        red3[warp * 3 + 0] = t0;
        red3[warp * 3 + 1] = t1;
        red3[warp * 3 + 2] = t2;
    }
    __syncthreads();
    if (tid < 3) {
        float s = 0.f;
#pragma unroll
        for (int w = 0; w < 16; w++) s += red3[w * 3 + tid];
        out[blk * 3 + tid] = pos[blk * 3 + tid] + s;
    }
}

// ---------------- launcher ----------------
extern "C" void kernel_launch(void* const* d_in, const int* in_sizes, int n_in,
                              void* d_out, int out_size) {
    const float* x_emb      = (const float*)d_in[0];
    const float* pair_emb   = (const float*)d_in[1];
    const float* pos        = (const float*)d_in[2];
    const float* coord_diff = (const float*)d_in[3];
    const float* pair_mask  = (const float*)d_in[5];
    const float* Wd         = (const float*)d_in[6];
    const float* bd         = (const float*)d_in[7];
    const float* W1         = (const float*)d_in[8];
    const float* b1         = (const float*)d_in[9];
    const float* W2         = (const float*)d_in[10];
    const float* b2         = (const float*)d_in[11];
    const float* W3         = (const float*)d_in[12];
    float* out = (float*)d_out;

    cudaFuncSetAttribute(pos_update_main,
                         cudaFuncAttributeMaxDynamicSharedMemorySize, SMEM_TOTAL);

    prep<<<129, 128>>>(x_emb, Wd, bd, W1, b1, W2);
    pos_update_main<<<NODES, 512, SMEM_TOTAL>>>(pair_emb, pos, coord_diff,
                                                pair_mask, b2, W3, out);
    (void)in_sizes; (void)n_in; (void)out_size;
}

// round 5
// speedup vs baseline: 1.5253x; 1.2283x over previous
#include <cuda_runtime.h>
#include <cuda_bf16.h>
#include <cstdint>

#define BDIM 8
#define NDIM 256
#define HDIM 128
#define INDIM 259
#define NODES (BDIM * NDIM)  // 2048

// ---------------- device scratch ----------------
__device__ float g_P[NODES * HDIM];                 // W1a @ x (per node, fp32)
__device__ __nv_bfloat16 g_Qbf[NODES * HDIM];       // W1b @ x (per node, bf16)
__device__ float g_b1eff[HDIM];                     // b1 + W1c @ bd
__device__ __nv_bfloat16 g_Wfuse[HDIM * HDIM];      // W1c @ Wd  [h][k]
__device__ __nv_bfloat16 g_W2bf[HDIM * HDIM];       // W2        [g][h]
__device__ float g_part[2 * NODES * 3];             // per half-CTA partial sums

// ---------------- helpers ----------------
__device__ __forceinline__ unsigned pack_bf2(float a, float b) {
    unsigned short lo = __bfloat16_as_ushort(__float2bfloat16_rn(a));
    unsigned short hi = __bfloat16_as_ushort(__float2bfloat16_rn(b));
    return (unsigned)lo | ((unsigned)hi << 16);
}
__device__ __forceinline__ float tanh_approx(float x) {
    float y; asm("tanh.approx.f32 %0, %1;" : "=f"(y) : "f"(x)); return y;
}
__device__ __forceinline__ float silu_f(float x) {
    float h = 0.5f * x;
    return fmaf(h, tanh_approx(h), h);
}
__device__ __forceinline__ uint32_t smem_u32(const void* p) {
    uint32_t a;
    asm("{ .reg .u64 t; cvta.to.shared.u64 t, %1; cvt.u32.u64 %0, t; }" : "=r"(a) : "l"(p));
    return a;
}

// ---------------- prep kernel (384 blocks, no serial tail) ----------------
// blocks [0,256):  P/Q for 8 nodes each
// blocks [256,384): fused weight row h = bx-256 (coalesced over k)
__global__ void prep(const float* __restrict__ x_emb, const float* __restrict__ Wd,
                     const float* __restrict__ bd, const float* __restrict__ W1,
                     const float* __restrict__ b1, const float* __restrict__ W2) {
    int t = threadIdx.x;
    int bx = blockIdx.x;
    if (bx >= 256) {
        int h = bx - 256;
        float w1c0 = W1[h * INDIM + 2 * HDIM + 0];
        float w1c1 = W1[h * INDIM + 2 * HDIM + 1];
        float w1c2 = W1[h * INDIM + 2 * HDIM + 2];
        float v = w1c0 * Wd[t] + w1c1 * Wd[HDIM + t] + w1c2 * Wd[2 * HDIM + t];
        g_Wfuse[h * HDIM + t] = __float2bfloat16_rn(v);
        g_W2bf[h * HDIM + t]  = __float2bfloat16_rn(W2[h * HDIM + t]);
        if (t == 0)
            g_b1eff[h] = b1[h] + w1c0 * bd[0] + w1c1 * bd[1] + w1c2 * bd[2];
        return;
    }
    __shared__ float xs[8][HDIM];
    int r0 = bx * 8;
    for (int idx = t; idx < 8 * HDIM; idx += 128)
        xs[idx >> 7][idx & 127] = x_emb[r0 * HDIM + idx];
    __syncthreads();

    float p[8], q[8];
#pragma unroll
    for (int ii = 0; ii < 8; ii++) { p[ii] = 0.f; q[ii] = 0.f; }
    const float* w1r = W1 + t * INDIM;
#pragma unroll 4
    for (int k = 0; k < HDIM; k++) {
        float wa = __ldg(&w1r[k]);
        float wb = __ldg(&w1r[HDIM + k]);
#pragma unroll
        for (int ii = 0; ii < 8; ii++) {
            float xv = xs[ii][k];
            p[ii] = fmaf(wa, xv, p[ii]);
            q[ii] = fmaf(wb, xv, q[ii]);
        }
    }
#pragma unroll
    for (int ii = 0; ii < 8; ii++) {
        g_P[(r0 + ii) * HDIM + t]   = p[ii];
        g_Qbf[(r0 + ii) * HDIM + t] = __float2bfloat16_rn(q[ii]);
    }
}

// ---------------- main fused kernel ----------------
// One CTA per (b, i, half): grid 4096, M = 128 rows of j per CTA.
// 512 threads = 16 warps in 4(M) x 4(N); each warp: 2 mt tiles x 4 nt tiles.
// 2 CTAs resident per SM (smem ~106 KB, <=64 regs) -> phase overlap.

#define PA 136                 // smem pitch in bf16 (128 + 8 pad)
#define ROWB (PA * 2)          // 272 bytes per row

#define OFF_AS   0             // 128*272 = 34816 (A tile, reused for H1)
#define OFF_B1   34816         // 34816 (Wfuse)
#define OFF_B2   69632         // 34816 (W2)
#define OFF_BIAS 104448        // float[128]  P[i] + b1eff
#define OFF_W3   104960        // float[128]
#define OFF_B2V  105472        // float[128]
#define OFF_SRED 105984        // float[128]
#define OFF_RED3 106496        // float[4*3] (pad to 64)
#define SMEM_TOTAL 106560

#define LDSM_X4(r0, r1, r2, r3, addr) \
    asm volatile("ldmatrix.sync.aligned.m8n8.x4.shared.b16 {%0,%1,%2,%3}, [%4];" \
                 : "=r"(r0), "=r"(r1), "=r"(r2), "=r"(r3) : "r"(addr))
#define LDSM_X2(r0, r1, addr) \
    asm volatile("ldmatrix.sync.aligned.m8n8.x2.shared.b16 {%0,%1}, [%2];" \
                 : "=r"(r0), "=r"(r1) : "r"(addr))

__device__ __forceinline__ void do_gemm(uint32_t aLane, uint32_t bLane,
                                        float acc[2][4][4]) {
#pragma unroll
    for (int ks = 0; ks < 8; ks++) {
        uint32_t a[2][4], b[4][2];
#pragma unroll
        for (int mt = 0; mt < 2; mt++)
            LDSM_X4(a[mt][0], a[mt][1], a[mt][2], a[mt][3],
                    aLane + mt * (16 * ROWB) + ks * 32);
#pragma unroll
        for (int nt = 0; nt < 4; nt++)
            LDSM_X2(b[nt][0], b[nt][1],
                    bLane + nt * (8 * ROWB) + ks * 32);
#pragma unroll
        for (int mt = 0; mt < 2; mt++)
#pragma unroll
            for (int nt = 0; nt < 4; nt++)
                asm volatile(
                    "mma.sync.aligned.m16n8k16.row.col.f32.bf16.bf16.f32 "
                    "{%0,%1,%2,%3}, {%4,%5,%6,%7}, {%8,%9}, {%0,%1,%2,%3};\n"
                    : "+f"(acc[mt][nt][0]), "+f"(acc[mt][nt][1]),
                      "+f"(acc[mt][nt][2]), "+f"(acc[mt][nt][3])
                    : "r"(a[mt][0]), "r"(a[mt][1]), "r"(a[mt][2]), "r"(a[mt][3]),
                      "r"(b[nt][0]), "r"(b[nt][1]));
    }
}

__global__ __launch_bounds__(512, 2)
void pos_update_main(const float* __restrict__ pair_emb,
                     const float* __restrict__ coord_diff,
                     const float* __restrict__ pair_mask,
                     const float* __restrict__ b2,
                     const float* __restrict__ W3) {
    extern __shared__ char smem[];
    __nv_bfloat16* As = reinterpret_cast<__nv_bfloat16*>(smem + OFF_AS);
    float* biasI = reinterpret_cast<float*>(smem + OFF_BIAS);
    float* w3s   = reinterpret_cast<float*>(smem + OFF_W3);
    float* b2s   = reinterpret_cast<float*>(smem + OFF_B2V);
    float* sRed  = reinterpret_cast<float*>(smem + OFF_SRED);
    float* red3  = reinterpret_cast<float*>(smem + OFF_RED3);

    const uint32_t sb = smem_u32(smem);
    const int tid  = threadIdx.x;
    const int lane = tid & 31;
    const int warp = tid >> 5;
    const int wm = warp >> 2, wn = warp & 3;
    const int g = lane >> 2, l4 = lane & 3;
    const int blk2 = blockIdx.x;              // (b*256+i)*2 + half
    const int blk  = blk2 >> 1;               // b*256 + i
    const int j0   = (blk2 & 1) << 7;         // 0 or 128
    const int bbase = blk & ~255;             // b*256

    const uint32_t aLane = sb + OFF_AS + (uint32_t)(wm * 32 + (lane & 15)) * ROWB
                              + (uint32_t)(lane >> 4) * 16;
    const uint32_t bLane1 = sb + OFF_B1 + (uint32_t)(wn * 32 + (lane & 7)) * ROWB
                              + (uint32_t)((lane >> 3) & 1) * 16;
    const uint32_t bLane2 = bLane1 + (OFF_B2 - OFF_B1);

    // ---- load phase ----
    {
        const float4* src = reinterpret_cast<const float4*>(
            pair_emb + ((size_t)blk * NDIM + j0) * HDIM);
#pragma unroll
        for (int it = 0; it < 8; it++) {
            int idx = tid + it * 512;         // 4096 float4
            float4 f = src[idx];
            int r = idx >> 5, c = (idx & 31) << 2;
            uint2 v; v.x = pack_bf2(f.x, f.y); v.y = pack_bf2(f.z, f.w);
            *reinterpret_cast<uint2*>(As + r * PA + c) = v;
        }
        const uint4* w1 = reinterpret_cast<const uint4*>(g_Wfuse);
        const uint4* w2 = reinterpret_cast<const uint4*>(g_W2bf);
        __nv_bfloat16* Bs1 = reinterpret_cast<__nv_bfloat16*>(smem + OFF_B1);
        __nv_bfloat16* Bs2 = reinterpret_cast<__nv_bfloat16*>(smem + OFF_B2);
#pragma unroll
        for (int it = 0; it < 4; it++) {
            int idx = tid + it * 512;         // 2048 uint4
            int r = idx >> 4, c = (idx & 15) << 3;
            *reinterpret_cast<uint4*>(Bs1 + r * PA + c) = w1[idx];
            *reinterpret_cast<uint4*>(Bs2 + r * PA + c) = w2[idx];
        }
        if (tid < 128) {
            biasI[tid] = g_P[(size_t)blk * HDIM + tid] + g_b1eff[tid];
            w3s[tid] = W3[tid];
            b2s[tid] = b2[tid];
            sRed[tid] = 0.f;
        }
    }
    __syncthreads();

    float acc[2][4][4];

    // ---- GEMM1 ----
#pragma unroll
    for (int mt = 0; mt < 2; mt++)
#pragma unroll
        for (int nt = 0; nt < 4; nt++)
#pragma unroll
            for (int e = 0; e < 4; e++) acc[mt][nt][e] = 0.f;

    do_gemm(aLane, bLane1, acc);

    __syncthreads();  // all reads of As done before H1 overwrite

    // ---- epilogue 1: silu(acc + biasI + Q[j]) -> H1 bf16 into As ----
    // Q read straight from gmem (bf16, L2-resident: reused by 512 CTAs/batch)
#pragma unroll
    for (int mt = 0; mt < 2; mt++) {
        int r = wm * 32 + mt * 16 + g;
        const __nv_bfloat16* qrow = g_Qbf + (size_t)(bbase + j0 + r) * HDIM;
#pragma unroll
        for (int nt = 0; nt < 4; nt++) {
            int c = wn * 32 + nt * 8 + l4 * 2;
            unsigned qlo = *reinterpret_cast<const unsigned*>(qrow + c);
            unsigned qhi = *reinterpret_cast<const unsigned*>(qrow + 8 * HDIM + c);
            __nv_bfloat162 ql = *reinterpret_cast<__nv_bfloat162*>(&qlo);
            __nv_bfloat162 qh = *reinterpret_cast<__nv_bfloat162*>(&qhi);
            float bc0 = biasI[c], bc1 = biasI[c + 1];
            float x0 = acc[mt][nt][0] + bc0 + __bfloat162float(ql.x);
            float x1 = acc[mt][nt][1] + bc1 + __bfloat162float(ql.y);
            float x2 = acc[mt][nt][2] + bc0 + __bfloat162float(qh.x);
            float x3 = acc[mt][nt][3] + bc1 + __bfloat162float(qh.y);
            *reinterpret_cast<unsigned*>(As + r * PA + c)       = pack_bf2(silu_f(x0), silu_f(x1));
            *reinterpret_cast<unsigned*>(As + (r + 8) * PA + c) = pack_bf2(silu_f(x2), silu_f(x3));
        }
    }
    __syncthreads();

    // ---- GEMM2 ----
#pragma unroll
    for (int mt = 0; mt < 2; mt++)
#pragma unroll
        for (int nt = 0; nt < 4; nt++)
#pragma unroll
            for (int e = 0; e < 4; e++) acc[mt][nt][e] = 0.f;

    do_gemm(aLane, bLane2, acc);

    // ---- epilogue 2: silu, dot with W3, reduce over columns ----
    float sAcc[2][2];
#pragma unroll
    for (int mt = 0; mt < 2; mt++) { sAcc[mt][0] = 0.f; sAcc[mt][1] = 0.f; }
#pragma unroll
    for (int mt = 0; mt < 2; mt++) {
#pragma unroll
        for (int nt = 0; nt < 4; nt++) {
            int c = wn * 32 + nt * 8 + l4 * 2;
            float bb0 = b2s[c], bb1 = b2s[c + 1];
            float w30 = w3s[c], w31 = w3s[c + 1];
            float y0 = silu_f(acc[mt][nt][0] + bb0);
            float y1 = silu_f(acc[mt][nt][1] + bb1);
            float y2 = silu_f(acc[mt][nt][2] + bb0);
            float y3 = silu_f(acc[mt][nt][3] + bb1);
            sAcc[mt][0] += y0 * w30 + y1 * w31;
            sAcc[mt][1] += y2 * w30 + y3 * w31;
        }
    }
#pragma unroll
    for (int mt = 0; mt < 2; mt++) {
#pragma unroll
        for (int hh = 0; hh < 2; hh++) {
            sAcc[mt][hh] += __shfl_xor_sync(0xffffffffu, sAcc[mt][hh], 1);
            sAcc[mt][hh] += __shfl_xor_sync(0xffffffffu, sAcc[mt][hh], 2);
        }
    }
    if (l4 == 0) {
#pragma unroll
        for (int mt = 0; mt < 2; mt++) {
            atomicAdd(&sRed[wm * 32 + mt * 16 + g],     sAcc[mt][0]);
            atomicAdd(&sRed[wm * 32 + mt * 16 + 8 + g], sAcc[mt][1]);
        }
    }
    __syncthreads();

    // ---- partial trans sum over this CTA's 128 j's ----
    float t0 = 0.f, t1 = 0.f, t2 = 0.f;
    if (tid < 128) {
        size_t jj = (size_t)blk * NDIM + j0 + tid;
        float sj = sRed[tid] * pair_mask[jj];
        const float* cd = coord_diff + jj * 3;
        t0 = cd[0] * sj; t1 = cd[1] * sj; t2 = cd[2] * sj;
    }
#pragma unroll
    for (int off = 16; off > 0; off >>= 1) {
        t0 += __shfl_down_sync(0xffffffffu, t0, off);
        t1 += __shfl_down_sync(0xffffffffu, t1, off);
        t2 += __shfl_down_sync(0xffffffffu, t2, off);
    }
    if (warp < 4 && lane == 0) {
        red3[warp * 3 + 0] = t0;
        red3[warp * 3 + 1] = t1;
        red3[warp * 3 + 2] = t2;
    }
    __syncthreads();
    if (tid < 3) {
        float s = red3[tid] + red3[3 + tid] + red3[6 + tid] + red3[9 + tid];
        g_part[(size_t)blk2 * 3 + tid] = s;
    }
}

// ---------------- combine kernel ----------------
__global__ void combine(const float* __restrict__ pos, float* __restrict__ out) {
    int i = blockIdx.x * blockDim.x + threadIdx.x;   // 0..6143
    if (i < NODES * 3) {
        int blk = i / 3, d = i - blk * 3;
        out[i] = pos[i] + g_part[blk * 6 + d] + g_part[blk * 6 + 3 + d];
    }
}

// ---------------- launcher ----------------
extern "C" void kernel_launch(void* const* d_in, const int* in_sizes, int n_in,
                              void* d_out, int out_size) {
    const float* x_emb      = (const float*)d_in[0];
    const float* pair_emb   = (const float*)d_in[1];
    const float* pos        = (const float*)d_in[2];
    const float* coord_diff = (const float*)d_in[3];
    const float* pair_mask  = (const float*)d_in[5];
    const float* Wd         = (const float*)d_in[6];
    const float* bd         = (const float*)d_in[7];
    const float* W1         = (const float*)d_in[8];
    const float* b1         = (const float*)d_in[9];
    const float* W2         = (const float*)d_in[10];
    const float* b2         = (const float*)d_in[11];
    const float* W3         = (const float*)d_in[12];
    float* out = (float*)d_out;

    cudaFuncSetAttribute(pos_update_main,
                         cudaFuncAttributeMaxDynamicSharedMemorySize, SMEM_TOTAL);

    prep<<<384, 128>>>(x_emb, Wd, bd, W1, b1, W2);
    pos_update_main<<<2 * NODES, 512, SMEM_TOTAL>>>(pair_emb, coord_diff,
                                                    pair_mask, b2, W3);
    combine<<<(NODES * 3 + 511) / 512, 512>>>(pos, out);
    (void)in_sizes; (void)n_in; (void)out_size;
}

// round 6
// speedup vs baseline: 1.6521x; 1.0831x over previous
#include <cuda_runtime.h>
#include <cuda_bf16.h>
#include <cstdint>

#define BDIM 8
#define NDIM 256
#define HDIM 128
#define INDIM 259
#define NODES (BDIM * NDIM)  // 2048

// ---------------- device scratch ----------------
__device__ float g_P[NODES * HDIM];                 // W1a @ x (per node, fp32)
__device__ __nv_bfloat16 g_Qbf[NODES * HDIM];       // W1b @ x (per node, bf16)
__device__ float g_b1eff[HDIM];                     // b1 + W1c @ bd
__device__ __nv_bfloat16 g_Wfuse[HDIM * HDIM];      // W1c @ Wd  [h][k]
__device__ __nv_bfloat16 g_W2bf[HDIM * HDIM];       // W2        [g][h]
__device__ float g_part[2 * NODES * 3];             // per half-CTA partial sums

// ---------------- helpers ----------------
__device__ __forceinline__ unsigned pack_bf2(float a, float b) {
    unsigned short lo = __bfloat16_as_ushort(__float2bfloat16_rn(a));
    unsigned short hi = __bfloat16_as_ushort(__float2bfloat16_rn(b));
    return (unsigned)lo | ((unsigned)hi << 16);
}
__device__ __forceinline__ float tanh_approx(float x) {
    float y; asm("tanh.approx.f32 %0, %1;" : "=f"(y) : "f"(x)); return y;
}
__device__ __forceinline__ float silu_f(float x) {
    float h = 0.5f * x;
    return fmaf(h, tanh_approx(h), h);
}
__device__ __forceinline__ uint32_t smem_u32(const void* p) {
    uint32_t a;
    asm("{ .reg .u64 t; cvta.to.shared.u64 t, %1; cvt.u32.u64 %0, t; }" : "=r"(a) : "l"(p));
    return a;
}

#define CP16(dst, src) \
    asm volatile("cp.async.cg.shared.global [%0], [%1], 16;" :: "r"(dst), "l"(src))
#define CP_COMMIT() asm volatile("cp.async.commit_group;")
#define CP_WAIT0()  asm volatile("cp.async.wait_group 0;")

// ---------------- prep kernel (coalesced, smem-staged) ----------------
// grid 128 x 256 threads.
// blocks [0,64):   P/Q for 32 nodes each, W1 staged through smem (coalesced)
// blocks [64,128): fused weight rows h = (bx-64)*2 + (t>>7)
__global__ __launch_bounds__(256)
void prep(const float* __restrict__ x_emb, const float* __restrict__ Wd,
          const float* __restrict__ bd, const float* __restrict__ W1,
          const float* __restrict__ b1, const float* __restrict__ W2) {
    int t = threadIdx.x;
    int bx = blockIdx.x;
    if (bx >= 64) {
        int h = ((bx - 64) << 1) + (t >> 7);
        int k = t & 127;
        float w1c0 = W1[h * INDIM + 2 * HDIM + 0];
        float w1c1 = W1[h * INDIM + 2 * HDIM + 1];
        float w1c2 = W1[h * INDIM + 2 * HDIM + 2];
        float v = w1c0 * Wd[k] + w1c1 * Wd[HDIM + k] + w1c2 * Wd[2 * HDIM + k];
        g_Wfuse[h * HDIM + k] = __float2bfloat16_rn(v);
        g_W2bf[h * HDIM + k]  = __float2bfloat16_rn(W2[h * HDIM + k]);
        if (k == 0)
            g_b1eff[h] = b1[h] + w1c0 * bd[0] + w1c1 * bd[1] + w1c2 * bd[2];
        return;
    }
    __shared__ float xs[32][HDIM];           // 16 KB
    __shared__ float wsA[16][129];           // k-chunk of W1a, [c][h]
    __shared__ float wsB[16][129];           // k-chunk of W1b, [c][h]

    int r0 = bx * 32;
    for (int idx = t; idx < 32 * HDIM; idx += 256)
        xs[idx >> 7][idx & 127] = x_emb[r0 * HDIM + idx];

    const int h = t & 127;
    const int nbase = (t >> 7) * 16;         // 0 or 16

    float p[16], q[16];
#pragma unroll
    for (int ii = 0; ii < 16; ii++) { p[ii] = 0.f; q[ii] = 0.f; }

#pragma unroll 1
    for (int c0 = 0; c0 < HDIM; c0 += 16) {
        __syncthreads();
        // coalesced staging: 128 rows x 16 cols, 64B segments
        for (int idx = t; idx < 2048; idx += 256) {
            int row = idx >> 4, c = idx & 15;
            wsA[c][row] = W1[row * INDIM + c0 + c];
            wsB[c][row] = W1[row * INDIM + HDIM + c0 + c];
        }
        __syncthreads();
#pragma unroll
        for (int c = 0; c < 16; c++) {
            float wa = wsA[c][h];
            float wb = wsB[c][h];
#pragma unroll
            for (int ii = 0; ii < 16; ii++) {
                float xv = xs[nbase + ii][c0 + c];
                p[ii] = fmaf(wa, xv, p[ii]);
                q[ii] = fmaf(wb, xv, q[ii]);
            }
        }
    }
#pragma unroll
    for (int ii = 0; ii < 16; ii++) {
        g_P[(size_t)(r0 + nbase + ii) * HDIM + h]   = p[ii];
        g_Qbf[(size_t)(r0 + nbase + ii) * HDIM + h] = __float2bfloat16_rn(q[ii]);
    }
}

// ---------------- main fused kernel ----------------
// One CTA per (b, i, half): grid 4096, M = 128 rows of j per CTA.
// 512 threads = 16 warps in 4(M) x 4(N). 2 CTAs/SM.

#define PA 136                 // smem pitch in bf16 (128 + 8 pad)
#define ROWB (PA * 2)          // 272 bytes per row

#define OFF_AS   0             // 128*272 = 34816 (A tile, reused for H1)
#define OFF_B1   34816         // 34816 (Wfuse)
#define OFF_B2   69632         // 34816 (W2)
#define OFF_BIAS 104448        // float[128]  P[i] + b1eff
#define OFF_W3   104960        // float[128]
#define OFF_B2V  105472        // float[128]
#define OFF_SRED 105984        // float[4*128] per-wn slices
#define OFF_RED3 108032        // float[4*3] pad
#define SMEM_TOTAL 108096

#define LDSM_X4(r0, r1, r2, r3, addr) \
    asm volatile("ldmatrix.sync.aligned.m8n8.x4.shared.b16 {%0,%1,%2,%3}, [%4];" \
                 : "=r"(r0), "=r"(r1), "=r"(r2), "=r"(r3) : "r"(addr))

__device__ __forceinline__ void do_gemm(uint32_t aLane, uint32_t bLane,
                                        float acc[2][4][4]) {
#pragma unroll
    for (int ks = 0; ks < 8; ks++) {
        uint32_t a[2][4], b[4][2];
#pragma unroll
        for (int mt = 0; mt < 2; mt++)
            LDSM_X4(a[mt][0], a[mt][1], a[mt][2], a[mt][3],
                    aLane + mt * (16 * ROWB) + ks * 32);
#pragma unroll
        for (int np = 0; np < 2; np++)
            LDSM_X4(b[2 * np][0], b[2 * np][1], b[2 * np + 1][0], b[2 * np + 1][1],
                    bLane + np * (16 * ROWB) + ks * 32);
#pragma unroll
        for (int mt = 0; mt < 2; mt++)
#pragma unroll
            for (int nt = 0; nt < 4; nt++)
                asm volatile(
                    "mma.sync.aligned.m16n8k16.row.col.f32.bf16.bf16.f32 "
                    "{%0,%1,%2,%3}, {%4,%5,%6,%7}, {%8,%9}, {%0,%1,%2,%3};\n"
                    : "+f"(acc[mt][nt][0]), "+f"(acc[mt][nt][1]),
                      "+f"(acc[mt][nt][2]), "+f"(acc[mt][nt][3])
                    : "r"(a[mt][0]), "r"(a[mt][1]), "r"(a[mt][2]), "r"(a[mt][3]),
                      "r"(b[nt][0]), "r"(b[nt][1]));
    }
}

__global__ __launch_bounds__(512, 2)
void pos_update_main(const float* __restrict__ pair_emb,
                     const float* __restrict__ coord_diff,
                     const float* __restrict__ pair_mask,
                     const float* __restrict__ b2,
                     const float* __restrict__ W3) {
    extern __shared__ char smem[];
    __nv_bfloat16* As = reinterpret_cast<__nv_bfloat16*>(smem + OFF_AS);
    float* biasI = reinterpret_cast<float*>(smem + OFF_BIAS);
    float* w3s   = reinterpret_cast<float*>(smem + OFF_W3);
    float* b2s   = reinterpret_cast<float*>(smem + OFF_B2V);
    float* sRedW = reinterpret_cast<float*>(smem + OFF_SRED);   // [4][128]
    float* red3  = reinterpret_cast<float*>(smem + OFF_RED3);

    const uint32_t sb = smem_u32(smem);
    const int tid  = threadIdx.x;
    const int lane = tid & 31;
    const int warp = tid >> 5;
    const int wm = warp >> 2, wn = warp & 3;
    const int g = lane >> 2, l4 = lane & 3;
    const int blk2 = blockIdx.x;              // (b*256+i)*2 + half
    const int blk  = blk2 >> 1;               // b*256 + i
    const int j0   = (blk2 & 1) << 7;         // 0 or 128
    const int bbase = blk & ~255;             // b*256

    // ldmatrix lane addresses
    const uint32_t aLane = sb + OFF_AS + (uint32_t)(wm * 32 + (lane & 15)) * ROWB
                              + (uint32_t)(lane >> 4) * 16;
    // B x4: lanes 0-7 -> rows(+0) k0, 8-15 -> rows(+0) k1, 16-23 -> rows(+8) k0, 24-31 -> rows(+8) k1
    const uint32_t bLane1 = sb + OFF_B1
        + (uint32_t)(wn * 32 + (lane & 7) + ((lane >> 4) << 3)) * ROWB
        + (uint32_t)((lane >> 3) & 1) * 16;
    const uint32_t bLane2 = bLane1 + (OFF_B2 - OFF_B1);

    // ---- load phase ----
    {
        // weights via cp.async (already bf16 in gmem)
        const char* w1 = reinterpret_cast<const char*>(g_Wfuse);
        const char* w2 = reinterpret_cast<const char*>(g_W2bf);
#pragma unroll
        for (int it = 0; it < 4; it++) {
            int idx = tid + it * 512;         // 2048 x 16B
            int r = idx >> 4, c = (idx & 15) << 3;
            uint32_t doff = (uint32_t)(r * PA + c) * 2;
            CP16(sb + OFF_B1 + doff, w1 + idx * 16);
            CP16(sb + OFF_B2 + doff, w2 + idx * 16);
        }
        CP_COMMIT();

        // A tile: fp32 -> bf16 via registers
        const float4* src = reinterpret_cast<const float4*>(
            pair_emb + ((size_t)blk * NDIM + j0) * HDIM);
#pragma unroll
        for (int it = 0; it < 8; it++) {
            int idx = tid + it * 512;         // 4096 float4
            float4 f = src[idx];
            int r = idx >> 5, c = (idx & 31) << 2;
            uint2 v; v.x = pack_bf2(f.x, f.y); v.y = pack_bf2(f.z, f.w);
            *reinterpret_cast<uint2*>(As + r * PA + c) = v;
        }
        if (tid < 128) {
            biasI[tid] = g_P[(size_t)blk * HDIM + tid] + g_b1eff[tid];
            w3s[tid] = W3[tid];
            b2s[tid] = b2[tid];
        }
        CP_WAIT0();
    }
    __syncthreads();

    float acc[2][4][4];

    // ---- GEMM1 ----
#pragma unroll
    for (int mt = 0; mt < 2; mt++)
#pragma unroll
        for (int nt = 0; nt < 4; nt++)
#pragma unroll
            for (int e = 0; e < 4; e++) acc[mt][nt][e] = 0.f;

    do_gemm(aLane, bLane1, acc);

    __syncthreads();  // all reads of As done before H1 overwrite

    // ---- epilogue 1: silu(acc + biasI + Q[j]) -> H1 bf16 into As ----
#pragma unroll
    for (int mt = 0; mt < 2; mt++) {
        int r = wm * 32 + mt * 16 + g;
        const __nv_bfloat16* qrow = g_Qbf + (size_t)(bbase + j0 + r) * HDIM;
#pragma unroll
        for (int nt = 0; nt < 4; nt++) {
            int c = wn * 32 + nt * 8 + l4 * 2;
            unsigned qlo = *reinterpret_cast<const unsigned*>(qrow + c);
            unsigned qhi = *reinterpret_cast<const unsigned*>(qrow + 8 * HDIM + c);
            __nv_bfloat162 ql = *reinterpret_cast<__nv_bfloat162*>(&qlo);
            __nv_bfloat162 qh = *reinterpret_cast<__nv_bfloat162*>(&qhi);
            float bc0 = biasI[c], bc1 = biasI[c + 1];
            float x0 = acc[mt][nt][0] + bc0 + __bfloat162float(ql.x);
            float x1 = acc[mt][nt][1] + bc1 + __bfloat162float(ql.y);
            float x2 = acc[mt][nt][2] + bc0 + __bfloat162float(qh.x);
            float x3 = acc[mt][nt][3] + bc1 + __bfloat162float(qh.y);
            *reinterpret_cast<unsigned*>(As + r * PA + c)       = pack_bf2(silu_f(x0), silu_f(x1));
            *reinterpret_cast<unsigned*>(As + (r + 8) * PA + c) = pack_bf2(silu_f(x2), silu_f(x3));
        }
    }
    __syncthreads();

    // ---- GEMM2 ----
#pragma unroll
    for (int mt = 0; mt < 2; mt++)
#pragma unroll
        for (int nt = 0; nt < 4; nt++)
#pragma unroll
            for (int e = 0; e < 4; e++) acc[mt][nt][e] = 0.f;

    do_gemm(aLane, bLane2, acc);

    // ---- epilogue 2: silu, dot with W3, per-wn slice write (no atomics) ----
    float sAcc[2][2];
#pragma unroll
    for (int mt = 0; mt < 2; mt++) { sAcc[mt][0] = 0.f; sAcc[mt][1] = 0.f; }
#pragma unroll
    for (int mt = 0; mt < 2; mt++) {
#pragma unroll
        for (int nt = 0; nt < 4; nt++) {
            int c = wn * 32 + nt * 8 + l4 * 2;
            float bb0 = b2s[c], bb1 = b2s[c + 1];
            float w30 = w3s[c], w31 = w3s[c + 1];
            float y0 = silu_f(acc[mt][nt][0] + bb0);
            float y1 = silu_f(acc[mt][nt][1] + bb1);
            float y2 = silu_f(acc[mt][nt][2] + bb0);
            float y3 = silu_f(acc[mt][nt][3] + bb1);
            sAcc[mt][0] += y0 * w30 + y1 * w31;
            sAcc[mt][1] += y2 * w30 + y3 * w31;
        }
    }
#pragma unroll
    for (int mt = 0; mt < 2; mt++) {
#pragma unroll
        for (int hh = 0; hh < 2; hh++) {
            sAcc[mt][hh] += __shfl_xor_sync(0xffffffffu, sAcc[mt][hh], 1);
            sAcc[mt][hh] += __shfl_xor_sync(0xffffffffu, sAcc[mt][hh], 2);
        }
    }
    if (l4 == 0) {
#pragma unroll
        for (int mt = 0; mt < 2; mt++) {
            sRedW[wn * 128 + wm * 32 + mt * 16 + g]     = sAcc[mt][0];
            sRedW[wn * 128 + wm * 32 + mt * 16 + 8 + g] = sAcc[mt][1];
        }
    }
    __syncthreads();

    // ---- partial trans sum over this CTA's 128 j's ----
    float t0 = 0.f, t1 = 0.f, t2 = 0.f;
    if (tid < 128) {
        size_t jj = (size_t)blk * NDIM + j0 + tid;
        float s = sRedW[tid] + sRedW[128 + tid] + sRedW[256 + tid] + sRedW[384 + tid];
        float sj = s * pair_mask[jj];
        const float* cd = coord_diff + jj * 3;
        t0 = cd[0] * sj; t1 = cd[1] * sj; t2 = cd[2] * sj;
    }
#pragma unroll
    for (int off = 16; off > 0; off >>= 1) {
        t0 += __shfl_down_sync(0xffffffffu, t0, off);
        t1 += __shfl_down_sync(0xffffffffu, t1, off);
        t2 += __shfl_down_sync(0xffffffffu, t2, off);
    }
    if (warp < 4 && lane == 0) {
        red3[warp * 3 + 0] = t0;
        red3[warp * 3 + 1] = t1;
        red3[warp * 3 + 2] = t2;
    }
    __syncthreads();
    if (tid < 3) {
        float s = red3[tid] + red3[3 + tid] + red3[6 + tid] + red3[9 + tid];
        g_part[(size_t)blk2 * 3 + tid] = s;
    }
}

// ---------------- combine kernel ----------------
__global__ void combine(const float* __restrict__ pos, float* __restrict__ out) {
    int i = blockIdx.x * blockDim.x + threadIdx.x;   // 0..6143
    if (i < NODES * 3) {
        int blk = i / 3, d = i - blk * 3;
        out[i] = pos[i] + g_part[blk * 6 + d] + g_part[blk * 6 + 3 + d];
    }
}

// ---------------- launcher ----------------
extern "C" void kernel_launch(void* const* d_in, const int* in_sizes, int n_in,
                              void* d_out, int out_size) {
    const float* x_emb      = (const float*)d_in[0];
    const float* pair_emb   = (const float*)d_in[1];
    const float* pos        = (const float*)d_in[2];
    const float* coord_diff = (const float*)d_in[3];
    const float* pair_mask  = (const float*)d_in[5];
    const float* Wd         = (const float*)d_in[6];
    const float* bd         = (const float*)d_in[7];
    const float* W1         = (const float*)d_in[8];
    const float* b1         = (const float*)d_in[9];
    const float* W2         = (const float*)d_in[10];
    const float* b2         = (const float*)d_in[11];
    const float* W3         = (const float*)d_in[12];
    float* out = (float*)d_out;

    cudaFuncSetAttribute(pos_update_main,
                         cudaFuncAttributeMaxDynamicSharedMemorySize, SMEM_TOTAL);

    prep<<<128, 256>>>(x_emb, Wd, bd, W1, b1, W2);
    pos_update_main<<<2 * NODES, 512, SMEM_TOTAL>>>(pair_emb, coord_diff,
                                                    pair_mask, b2, W3);
    combine<<<(NODES * 3 + 511) / 512, 512>>>(pos, out);
    (void)in_sizes; (void)n_in; (void)out_size;
}

// round 8
// speedup vs baseline: 1.8268x; 1.1057x over previous
#include <cuda_runtime.h>
#include <cuda_bf16.h>
#include <cstdint>

#define BDIM 8
#define NDIM 256
#define HDIM 128
#define INDIM 259
#define NODES (BDIM * NDIM)  // 2048

// ---------------- device scratch ----------------
__device__ float g_P[NODES * HDIM];                 // W1a @ x (per node, fp32)
__device__ __nv_bfloat16 g_Qbf[NODES * HDIM];       // W1b @ x (per node, bf16)
__device__ float g_b1eff[HDIM];                     // b1 + W1c @ bd
__device__ __nv_bfloat16 g_Wfuse[HDIM * HDIM];      // W1c @ Wd  [h][k]
__device__ __nv_bfloat16 g_W2bf[HDIM * HDIM];       // W2        [g][h]
__device__ float g_W1aT[HDIM * HDIM];               // W1a^T [k][h]
__device__ float g_W1bT[HDIM * HDIM];               // W1b^T [k][h]
__device__ float g_part[2 * NODES * 3];             // per half-CTA partial sums

// ---------------- helpers ----------------
__device__ __forceinline__ unsigned pack_bf2(float lo, float hi) {
    unsigned r;
    asm("cvt.rn.bf16x2.f32 %0, %1, %2;" : "=r"(r) : "f"(hi), "f"(lo));
    return r;
}
__device__ __forceinline__ float tanh_approx(float x) {
    float y; asm("tanh.approx.f32 %0, %1;" : "=f"(y) : "f"(x)); return y;
}
__device__ __forceinline__ float silu_f(float x) {
    float h = 0.5f * x;
    return fmaf(h, tanh_approx(h), h);
}
__device__ __forceinline__ uint32_t smem_u32(const void* p) {
    uint32_t a;
    asm("{ .reg .u64 t; cvta.to.shared.u64 t, %1; cvt.u32.u64 %0, t; }" : "=r"(a) : "l"(p));
    return a;
}

#define CP16(dst, src) \
    asm volatile("cp.async.cg.shared.global [%0], [%1], 16;" :: "r"(dst), "l"(src))
#define CP_COMMIT() asm volatile("cp.async.commit_group;")
#define CP_WAIT0()  asm volatile("cp.async.wait_group 0;")
#define BAR_GROUP(id) \
    asm volatile("bar.sync %0, 128;" :: "r"(id) : "memory")

// ---------------- prep_w: fused weights + W1 transpose (128 blocks) ----------------
__global__ __launch_bounds__(256)
void prep_w(const float* __restrict__ Wd, const float* __restrict__ bd,
            const float* __restrict__ W1, const float* __restrict__ b1,
            const float* __restrict__ W2) {
    int h = blockIdx.x;
    int t = threadIdx.x;
    if (t < 128) {
        int k = t;
        float w1c0 = W1[h * INDIM + 2 * HDIM + 0];
        float w1c1 = W1[h * INDIM + 2 * HDIM + 1];
        float w1c2 = W1[h * INDIM + 2 * HDIM + 2];
        float v = w1c0 * Wd[k] + w1c1 * Wd[HDIM + k] + w1c2 * Wd[2 * HDIM + k];
        g_Wfuse[h * HDIM + k] = __float2bfloat16_rn(v);
        g_W2bf[h * HDIM + k]  = __float2bfloat16_rn(W2[h * HDIM + k]);
        g_W1aT[k * HDIM + h]  = W1[h * INDIM + k];
        if (k == 0)
            g_b1eff[h] = b1[h] + w1c0 * bd[0] + w1c1 * bd[1] + w1c2 * bd[2];
    } else {
        int k = t - 128;
        g_W1bT[k * HDIM + h] = W1[h * INDIM + HDIM + k];
    }
}

// ---------------- prep_pq: per-node P/Q (256 blocks x 256 thr, coalesced) ----------------
__global__ __launch_bounds__(256)
void prep_pq(const float* __restrict__ x_emb) {
    __shared__ float xs[8][HDIM];
    int t = threadIdx.x;
    int r0 = blockIdx.x * 8;
    for (int idx = t; idx < 8 * HDIM; idx += 256)
        xs[idx >> 7][idx & 127] = x_emb[r0 * HDIM + idx];
    __syncthreads();

    const int h = t & 127;
    const int n0 = (t >> 7) * 4;

    float p[4] = {0.f, 0.f, 0.f, 0.f};
    float q[4] = {0.f, 0.f, 0.f, 0.f};
#pragma unroll 4
    for (int k = 0; k < HDIM; k++) {
        float wa = g_W1aT[k * HDIM + h];
        float wb = g_W1bT[k * HDIM + h];
#pragma unroll
        for (int ii = 0; ii < 4; ii++) {
            float xv = xs[n0 + ii][k];
            p[ii] = fmaf(wa, xv, p[ii]);
            q[ii] = fmaf(wb, xv, q[ii]);
        }
    }
#pragma unroll
    for (int ii = 0; ii < 4; ii++) {
        g_P[(size_t)(r0 + n0 + ii) * HDIM + h]   = p[ii];
        g_Qbf[(size_t)(r0 + n0 + ii) * HDIM + h] = __float2bfloat16_rn(q[ii]);
    }
}

// ---------------- main fused kernel ----------------
// One CTA per (b, i, half): grid 4096, M = 128 rows of j per CTA.
// 512 threads = 16 warps in 4(M=wm) x 4(N=wn). 2 CTAs/SM.
// Phase chain GEMM1 -> epi1 -> GEMM2 synchronized per wm-group (4 warps,
// named barrier 1+wm): the 4 groups pipeline independently.

#define PA 136                 // smem pitch in bf16 (128 + 8 pad)
#define ROWB (PA * 2)          // 272 bytes per row

#define OFF_AS   0             // 128*272 = 34816 (A tile, reused for H1)
#define OFF_B1   34816         // 34816 (Wfuse)
#define OFF_B2   69632         // 34816 (W2)
#define OFF_BIAS 104448        // float[128]  P[i] + b1eff
#define OFF_W3   104960        // float[128]
#define OFF_B2V  105472        // float[128]
#define OFF_SRED 105984        // float[4*128] per-wn slices
#define OFF_RED3 108032        // float[4*3] pad
#define SMEM_TOTAL 108096

#define LDSM_X4(r0, r1, r2, r3, addr) \
    asm volatile("ldmatrix.sync.aligned.m8n8.x4.shared.b16 {%0,%1,%2,%3}, [%4];" \
                 : "=r"(r0), "=r"(r1), "=r"(r2), "=r"(r3) : "r"(addr))

__device__ __forceinline__ void do_gemm(uint32_t aLane, uint32_t bLane,
                                        float acc[2][4][4]) {
#pragma unroll
    for (int ks = 0; ks < 8; ks++) {
        uint32_t a[2][4], b[4][2];
#pragma unroll
        for (int mt = 0; mt < 2; mt++)
            LDSM_X4(a[mt][0], a[mt][1], a[mt][2], a[mt][3],
                    aLane + mt * (16 * ROWB) + ks * 32);
#pragma unroll
        for (int np = 0; np < 2; np++)
            LDSM_X4(b[2 * np][0], b[2 * np][1], b[2 * np + 1][0], b[2 * np + 1][1],
                    bLane + np * (16 * ROWB) + ks * 32);
#pragma unroll
        for (int mt = 0; mt < 2; mt++)
#pragma unroll
            for (int nt = 0; nt < 4; nt++)
                asm volatile(
                    "mma.sync.aligned.m16n8k16.row.col.f32.bf16.bf16.f32 "
                    "{%0,%1,%2,%3}, {%4,%5,%6,%7}, {%8,%9}, {%0,%1,%2,%3};\n"
                    : "+f"(acc[mt][nt][0]), "+f"(acc[mt][nt][1]),
                      "+f"(acc[mt][nt][2]), "+f"(acc[mt][nt][3])
                    : "r"(a[mt][0]), "r"(a[mt][1]), "r"(a[mt][2]), "r"(a[mt][3]),
                      "r"(b[nt][0]), "r"(b[nt][1]));
    }
}

__global__ __launch_bounds__(512, 2)
void pos_update_main(const float* __restrict__ pair_emb,
                     const float* __restrict__ coord_diff,
                     const float* __restrict__ pair_mask,
                     const float* __restrict__ b2,
                     const float* __restrict__ W3) {
    extern __shared__ char smem[];
    __nv_bfloat16* As = reinterpret_cast<__nv_bfloat16*>(smem + OFF_AS);
    float* biasI = reinterpret_cast<float*>(smem + OFF_BIAS);
    float* w3s   = reinterpret_cast<float*>(smem + OFF_W3);
    float* b2s   = reinterpret_cast<float*>(smem + OFF_B2V);
    float* sRedW = reinterpret_cast<float*>(smem + OFF_SRED);   // [4][128]
    float* red3  = reinterpret_cast<float*>(smem + OFF_RED3);

    const uint32_t sb = smem_u32(smem);
    const int tid  = threadIdx.x;
    const int lane = tid & 31;
    const int warp = tid >> 5;
    const int wm = warp >> 2, wn = warp & 3;
    const int g = lane >> 2, l4 = lane & 3;
    const int blk2 = blockIdx.x;              // (b*256+i)*2 + half
    const int blk  = blk2 >> 1;               // b*256 + i
    const int j0   = (blk2 & 1) << 7;         // 0 or 128
    const int bbase = blk & ~255;             // b*256

    const uint32_t aLane = sb + OFF_AS + (uint32_t)(wm * 32 + (lane & 15)) * ROWB
                              + (uint32_t)(lane >> 4) * 16;
    const uint32_t bLane1 = sb + OFF_B1
        + (uint32_t)(wn * 32 + (lane & 7) + ((lane >> 4) << 3)) * ROWB
        + (uint32_t)((lane >> 3) & 1) * 16;
    const uint32_t bLane2 = bLane1 + (OFF_B2 - OFF_B1);

    // ---- load phase ----
    {
        const char* w1 = reinterpret_cast<const char*>(g_Wfuse);
        const char* w2 = reinterpret_cast<const char*>(g_W2bf);
#pragma unroll
        for (int it = 0; it < 4; it++) {
            int idx = tid + it * 512;         // 2048 x 16B
            int r = idx >> 4, c = (idx & 15) << 3;
            uint32_t doff = (uint32_t)(r * PA + c) * 2;
            CP16(sb + OFF_B1 + doff, w1 + idx * 16);
            CP16(sb + OFF_B2 + doff, w2 + idx * 16);
        }
        CP_COMMIT();

        const float4* src = reinterpret_cast<const float4*>(
            pair_emb + ((size_t)blk * NDIM + j0) * HDIM);
#pragma unroll
        for (int it = 0; it < 8; it++) {
            int idx = tid + it * 512;         // 4096 float4
            float4 f = src[idx];
            int r = idx >> 5, c = (idx & 31) << 2;
            uint2 v; v.x = pack_bf2(f.x, f.y); v.y = pack_bf2(f.z, f.w);
            *reinterpret_cast<uint2*>(As + r * PA + c) = v;
        }
        if (tid < 128) {
            biasI[tid] = g_P[(size_t)blk * HDIM + tid] + g_b1eff[tid];
            w3s[tid] = W3[tid];
            b2s[tid] = b2[tid];
        }
        CP_WAIT0();
    }
    __syncthreads();

    float acc[2][4][4];

    // ---- GEMM1 ----
#pragma unroll
    for (int mt = 0; mt < 2; mt++)
#pragma unroll
        for (int nt = 0; nt < 4; nt++)
#pragma unroll
            for (int e = 0; e < 4; e++) acc[mt][nt][e] = 0.f;

    do_gemm(aLane, bLane1, acc);

    // wm-group barrier: the 4 warps sharing rows [wm*32, wm*32+32) must all
    // finish GEMM1 A-reads before any of them overwrites those rows with H1.
    BAR_GROUP(1 + wm);

    // ---- epilogue 1: silu(acc + biasI + Q[j]) -> H1 bf16 into As ----
    // (this warp writes only columns [wn*32, wn*32+32) of its group's rows)
#pragma unroll
    for (int mt = 0; mt < 2; mt++) {
        int r = wm * 32 + mt * 16 + g;
        const __nv_bfloat16* qrow = g_Qbf + (size_t)(bbase + j0 + r) * HDIM;
#pragma unroll
        for (int nt = 0; nt < 4; nt++) {
            int c = wn * 32 + nt * 8 + l4 * 2;
            unsigned qlo = *reinterpret_cast<const unsigned*>(qrow + c);
            unsigned qhi = *reinterpret_cast<const unsigned*>(qrow + 8 * HDIM + c);
            __nv_bfloat162 ql = *reinterpret_cast<__nv_bfloat162*>(&qlo);
            __nv_bfloat162 qh = *reinterpret_cast<__nv_bfloat162*>(&qhi);
            float bc0 = biasI[c], bc1 = biasI[c + 1];
            float x0 = acc[mt][nt][0] + bc0 + __bfloat162float(ql.x);
            float x1 = acc[mt][nt][1] + bc1 + __bfloat162float(ql.y);
            float x2 = acc[mt][nt][2] + bc0 + __bfloat162float(qh.x);
            float x3 = acc[mt][nt][3] + bc1 + __bfloat162float(qh.y);
            *reinterpret_cast<unsigned*>(As + r * PA + c)       = pack_bf2(silu_f(x0), silu_f(x1));
            *reinterpret_cast<unsigned*>(As + (r + 8) * PA + c) = pack_bf2(silu_f(x2), silu_f(x3));
        }
    }

    // wm-group barrier: all 4 column slices of H1 must be written before
    // this warp's GEMM2 reads the full K range of its group's rows.
    BAR_GROUP(1 + wm);

    // ---- GEMM2 ----
#pragma unroll
    for (int mt = 0; mt < 2; mt++)
#pragma unroll
        for (int nt = 0; nt < 4; nt++)
#pragma unroll
            for (int e = 0; e < 4; e++) acc[mt][nt][e] = 0.f;

    do_gemm(aLane, bLane2, acc);

    // ---- epilogue 2: silu, dot with W3, per-wn slice write (no atomics) ----
    float sAcc[2][2];
#pragma unroll
    for (int mt = 0; mt < 2; mt++) { sAcc[mt][0] = 0.f; sAcc[mt][1] = 0.f; }
#pragma unroll
    for (int mt = 0; mt < 2; mt++) {
#pragma unroll
        for (int nt = 0; nt < 4; nt++) {
            int c = wn * 32 + nt * 8 + l4 * 2;
            float bb0 = b2s[c], bb1 = b2s[c + 1];
            float w30 = w3s[c], w31 = w3s[c + 1];
            float y0 = silu_f(acc[mt][nt][0] + bb0);
            float y1 = silu_f(acc[mt][nt][1] + bb1);
            float y2 = silu_f(acc[mt][nt][2] + bb0);
            float y3 = silu_f(acc[mt][nt][3] + bb1);
            sAcc[mt][0] += y0 * w30 + y1 * w31;
            sAcc[mt][1] += y2 * w30 + y3 * w31;
        }
    }
#pragma unroll
    for (int mt = 0; mt < 2; mt++) {
#pragma unroll
        for (int hh = 0; hh < 2; hh++) {
            sAcc[mt][hh] += __shfl_xor_sync(0xffffffffu, sAcc[mt][hh], 1);
            sAcc[mt][hh] += __shfl_xor_sync(0xffffffffu, sAcc[mt][hh], 2);
        }
    }
    if (l4 == 0) {
#pragma unroll
        for (int mt = 0; mt < 2; mt++) {
            sRedW[wn * 128 + wm * 32 + mt * 16 + g]     = sAcc[mt][0];
            sRedW[wn * 128 + wm * 32 + mt * 16 + 8 + g] = sAcc[mt][1];
        }
    }
    __syncthreads();

    // ---- partial trans sum over this CTA's 128 j's ----
    float t0 = 0.f, t1 = 0.f, t2 = 0.f;
    if (tid < 128) {
        size_t jj = (size_t)blk * NDIM + j0 + tid;
        float s = sRedW[tid] + sRedW[128 + tid] + sRedW[256 + tid] + sRedW[384 + tid];
        float sj = s * pair_mask[jj];
        const float* cd = coord_diff + jj * 3;
        t0 = cd[0] * sj; t1 = cd[1] * sj; t2 = cd[2] * sj;
    }
#pragma unroll
    for (int off = 16; off > 0; off >>= 1) {
        t0 += __shfl_down_sync(0xffffffffu, t0, off);
        t1 += __shfl_down_sync(0xffffffffu, t1, off);
        t2 += __shfl_down_sync(0xffffffffu, t2, off);
    }
    if (warp < 4 && lane == 0) {
        red3[warp * 3 + 0] = t0;
        red3[warp * 3 + 1] = t1;
        red3[warp * 3 + 2] = t2;
    }
    __syncthreads();
    if (tid < 3) {
        float s = red3[tid] + red3[3 + tid] + red3[6 + tid] + red3[9 + tid];
        g_part[(size_t)blk2 * 3 + tid] = s;
    }
}

// ---------------- combine kernel ----------------
__global__ void combine(const float* __restrict__ pos, float* __restrict__ out) {
    int i = blockIdx.x * blockDim.x + threadIdx.x;   // 0..6143
    if (i < NODES * 3) {
        int blk = i / 3, d = i - blk * 3;
        out[i] = pos[i] + g_part[blk * 6 + d] + g_part[blk * 6 + 3 + d];
    }
}

// ---------------- launcher ----------------
extern "C" void kernel_launch(void* const* d_in, const int* in_sizes, int n_in,
                              void* d_out, int out_size) {
    const float* x_emb      = (const float*)d_in[0];
    const float* pair_emb   = (const float*)d_in[1];
    const float* pos        = (const float*)d_in[2];
    const float* coord_diff = (const float*)d_in[3];
    const float* pair_mask  = (const float*)d_in[5];
    const float* Wd         = (const float*)d_in[6];
    const float* bd         = (const float*)d_in[7];
    const float* W1         = (const float*)d_in[8];
    const float* b1         = (const float*)d_in[9];
    const float* W2         = (const float*)d_in[10];
    const float* b2         = (const float*)d_in[11];
    const float* W3         = (const float*)d_in[12];
    float* out = (float*)d_out;

    cudaFuncSetAttribute(pos_update_main,
                         cudaFuncAttributeMaxDynamicSharedMemorySize, SMEM_TOTAL);

    prep_w<<<128, 256>>>(Wd, bd, W1, b1, W2);
    prep_pq<<<256, 256>>>(x_emb);
    pos_update_main<<<2 * NODES, 512, SMEM_TOTAL>>>(pair_emb, coord_diff,
                                                    pair_mask, b2, W3);
    combine<<<(NODES * 3 + 511) / 512, 512>>>(pos, out);
    (void)in_sizes; (void)n_in; (void)out_size;
}